// round 2
// baseline (speedup 1.0000x reference)
#include <cuda_runtime.h>
#include <math.h>

// Problem constants
#define NB 32          // batch
#define CC 256         // channels
#define HW 4096        // H*W
#define GG 4           // groups
#define DD 64          // channels per group
#define MMTOT 131072   // m = NB*HW
#define CHUNKS 4       // hw chunks per (n,g)
#define TK 1024        // hw per chunk
#define SUB 64         // k-subtile
#define NSUB 16        // TK/SUB
#define LDA 68         // padded smem row stride

// Scratch (device globals; no allocation allowed)
__device__ float g_sum[NB*CC];
__device__ float g_sumsq[NB*CC];
__device__ float g_gram[GG*DD*DD];
__device__ float g_sigman[GG*DD*DD];
__device__ float g_pw[GG*DD*DD];     // w * P per group
__device__ float g_y[NB*CC];         // sigmoid MLP output
__device__ float g_varsum;           // sum of x_var over all (n,c)

// ---------------------------------------------------------------------------
__global__ void k_zero() {
    int i = blockIdx.x * blockDim.x + threadIdx.x;
    if (i < NB*CC) { g_sum[i] = 0.f; g_sumsq[i] = 0.f; }
    if (i < GG*DD*DD) g_gram[i] = 0.f;
    if (i == 0) g_varsum = 0.f;
}

// ---------------------------------------------------------------------------
// Pass 1: read X once. Per-(n,c) sum & sumsq (for x_var) + per-group Gram
// partials (uncentered: Sigma computed later as Gram - m*mu*mu^T).
// Grid: (CHUNKS, GG, NB), 256 threads.
__global__ __launch_bounds__(256) void k_statsgram(const float* __restrict__ X) {
    __shared__ float As[SUB][LDA];   // As[k][ch] (transposed tile)
    int n = blockIdx.z, g = blockIdx.y, ch = blockIdx.x;
    const float* base = X + ((size_t)(n*CC + g*DD))*HW + (size_t)ch*TK;
    int t  = threadIdx.x;
    int tx = t & 15, ty = t >> 4;

    float acc[4][4];
    #pragma unroll
    for (int i = 0; i < 4; i++)
        #pragma unroll
        for (int j = 0; j < 4; j++) acc[i][j] = 0.f;
    float s1[4] = {0.f,0.f,0.f,0.f}, s2[4] = {0.f,0.f,0.f,0.f};

    for (int sub = 0; sub < NSUB; sub++) {
        // load 64x64 tile (coalesced float4), transpose into As[k][ch]
        #pragma unroll
        for (int i = 0; i < 4; i++) {
            int idx = t + i*256;          // 0..1023 float4 slots
            int c   = idx >> 4;           // channel within group
            int k4  = (idx & 15) << 2;    // k offset
            float4 v = *(const float4*)(base + (size_t)c*HW + sub*SUB + k4);
            As[k4+0][c] = v.x; As[k4+1][c] = v.y;
            As[k4+2][c] = v.z; As[k4+3][c] = v.w;
            s1[i] += v.x + v.y + v.z + v.w;
            s2[i] += v.x*v.x + v.y*v.y + v.z*v.z + v.w*v.w;
        }
        __syncthreads();
        // Gram tile: 4x4 register blocking
        #pragma unroll 4
        for (int k = 0; k < SUB; k++) {
            float4 av = *(const float4*)&As[k][ty<<2];
            float4 bv = *(const float4*)&As[k][tx<<2];
            float a[4] = {av.x, av.y, av.z, av.w};
            float b[4] = {bv.x, bv.y, bv.z, bv.w};
            #pragma unroll
            for (int ri = 0; ri < 4; ri++)
                #pragma unroll
                for (int cj = 0; cj < 4; cj++)
                    acc[ri][cj] += a[ri]*b[cj];
        }
        __syncthreads();
    }

    // reduce per-channel sums across the 16 threads sharing a channel
    #pragma unroll
    for (int i = 0; i < 4; i++) {
        float a = s1[i], b = s2[i];
        #pragma unroll
        for (int off = 8; off >= 1; off >>= 1) {
            a += __shfl_xor_sync(0xffffffffu, a, off, 16);
            b += __shfl_xor_sync(0xffffffffu, b, off, 16);
        }
        if ((t & 15) == 0) {
            int c = (t >> 4) + i*16;
            atomicAdd(&g_sum[n*CC + g*DD + c], a);
            atomicAdd(&g_sumsq[n*CC + g*DD + c], b);
        }
    }
    // Gram accumulation
    #pragma unroll
    for (int ri = 0; ri < 4; ri++)
        #pragma unroll
        for (int cj = 0; cj < 4; cj++)
            atomicAdd(&g_gram[g*DD*DD + ((ty<<2)+ri)*DD + (tx<<2)+cj], acc[ri][cj]);
}

// ---------------------------------------------------------------------------
// Per-n MLP: x_var -> fc1 -> LayerNorm -> relu -> fc2 -> sigmoid = y
// Also accumulates sum(x_var) for the global scale. Grid: NB blocks, 256 thr.
__global__ __launch_bounds__(256) void k_reweight(const float* __restrict__ fc1,
                                                  const float* __restrict__ lng,
                                                  const float* __restrict__ lnb,
                                                  const float* __restrict__ fc2) {
    __shared__ float sv[CC];
    __shared__ float sh[DD];
    __shared__ float warpsum[8];
    __shared__ float sred[2];
    int n = blockIdx.x, t = threadIdx.x;

    float s  = g_sum[n*CC + t];
    float ss = g_sumsq[n*CC + t];
    float var = (ss - s*s*(1.0f/HW)) * (1.0f/(HW - 1));   // ddof=1
    sv[t] = var;

    float vs = var;
    #pragma unroll
    for (int o = 16; o; o >>= 1) vs += __shfl_xor_sync(0xffffffffu, vs, o);
    if ((t & 31) == 0) warpsum[t >> 5] = vs;
    __syncthreads();
    if (t == 0) {
        float tot = 0.f;
        #pragma unroll
        for (int i = 0; i < 8; i++) tot += warpsum[i];
        atomicAdd(&g_varsum, tot);
    }

    // h[k] = sum_c x_var[c] * fc1[k, c] ; warp w handles k = w*8..w*8+7
    int w = t >> 5, l = t & 31;
    for (int kk = 0; kk < 8; kk++) {
        int k = w*8 + kk;
        float acc = 0.f;
        for (int c = l; c < CC; c += 32) acc += sv[c] * fc1[k*CC + c];
        #pragma unroll
        for (int o = 16; o; o >>= 1) acc += __shfl_xor_sync(0xffffffffu, acc, o);
        if (l == 0) sh[k] = acc;
    }
    __syncthreads();

    // LayerNorm over 64 (biased var)
    if (w == 0) {
        float h1 = sh[l], h2 = sh[l + 32];
        float su = h1 + h2, q = h1*h1 + h2*h2;
        #pragma unroll
        for (int o = 16; o; o >>= 1) {
            su += __shfl_xor_sync(0xffffffffu, su, o);
            q  += __shfl_xor_sync(0xffffffffu, q,  o);
        }
        float mu = su * (1.0f/DD);
        float vr = q * (1.0f/DD) - mu*mu;
        if (l == 0) { sred[0] = mu; sred[1] = rsqrtf(vr + 1e-5f); }
    }
    __syncthreads();
    float mu = sred[0], rstd = sred[1];
    if (t < DD) {
        float hh = (sh[t] - mu) * rstd * lng[t] + lnb[t];
        sh[t] = fmaxf(hh, 0.f);
    }
    __syncthreads();

    // y[c] = sigmoid(sum_k h[k] * fc2[c, k])
    float acc = 0.f;
    #pragma unroll 8
    for (int k = 0; k < DD; k++) acc += sh[k] * fc2[t*DD + k];
    g_y[n*CC + t] = 1.0f / (1.0f + expf(-acc));
}

// ---------------------------------------------------------------------------
// Sigma_N per group: Sigma = (1/m)I + EPS*(Gram - m*mu*mu^T); normalize by trace.
__global__ __launch_bounds__(256) void k_sigma() {
    int g = blockIdx.x, t = threadIdx.x;
    __shared__ float smean[DD];
    __shared__ float sS[DD*DD];
    __shared__ float strace;
    if (t < DD) {
        float s = 0.f;
        #pragma unroll 8
        for (int n = 0; n < NB; n++) s += g_sum[n*CC + g*DD + t];
        smean[t] = s * (1.0f/(float)MMTOT);
    }
    if (t == 0) strace = 0.f;
    __syncthreads();
    float tr = 0.f;
    #pragma unroll
    for (int i = 0; i < 16; i++) {
        int idx = t + i*256;
        int r = idx >> 6, c = idx & 63;
        float v = 1e-5f * (g_gram[g*DD*DD + idx] - (float)MMTOT * smean[r] * smean[c]);
        if (r == c) { v += 1.0f/(float)MMTOT; tr += v; }
        sS[idx] = v;
    }
    #pragma unroll
    for (int o = 16; o; o >>= 1) tr += __shfl_xor_sync(0xffffffffu, tr, o);
    if ((t & 31) == 0) atomicAdd(&strace, tr);
    __syncthreads();
    float rtr = 1.0f / strace;
    #pragma unroll
    for (int i = 0; i < 16; i++) {
        int idx = t + i*256;
        g_sigman[g*DD*DD + idx] = sS[idx] * rtr;
    }
}

// ---------------------------------------------------------------------------
// Newton-Schulz (T=3): P = -0.5 P + 1.5 (P@P@P@Sigma_N). One block per group.
// Exactly 3 smem matrices (48 KB): P, S, T. P^3 overwrites P via register staging.
__device__ __forceinline__ void mm_acc(float acc[4][4], const float* A,
                                       const float* B, int tx, int ty) {
    #pragma unroll
    for (int i = 0; i < 4; i++)
        #pragma unroll
        for (int j = 0; j < 4; j++) acc[i][j] = 0.f;
    #pragma unroll 8
    for (int k = 0; k < DD; k++) {
        float a[4];
        #pragma unroll
        for (int ri = 0; ri < 4; ri++) a[ri] = A[((ty<<2)+ri)*DD + k];
        float4 bv = *(const float4*)&B[k*DD + (tx<<2)];
        float b[4] = {bv.x, bv.y, bv.z, bv.w};
        #pragma unroll
        for (int ri = 0; ri < 4; ri++)
            #pragma unroll
            for (int cj = 0; cj < 4; cj++)
                acc[ri][cj] += a[ri]*b[cj];
    }
}

__global__ __launch_bounds__(256) void k_ns(const float* __restrict__ xw) {
    __shared__ float sm[3*DD*DD];   // 49152 B
    float* sP = sm;
    float* sS = sm + DD*DD;
    float* sT = sm + 2*DD*DD;
    int g = blockIdx.x, t = threadIdx.x;
    int tx = t & 15, ty = t >> 4;

    #pragma unroll
    for (int i = 0; i < 16; i++) {
        int idx = t + i*256;
        sS[idx] = g_sigman[g*DD*DD + idx];
        sP[idx] = ((idx >> 6) == (idx & 63)) ? 1.0f : 0.0f;
    }
    __syncthreads();

    for (int it = 0; it < 3; it++) {
        float t1[4][4];
        mm_acc(t1, sP, sP, tx, ty);                 // T = P@P
        #pragma unroll
        for (int ri = 0; ri < 4; ri++)
            #pragma unroll
            for (int cj = 0; cj < 4; cj++)
                sT[((ty<<2)+ri)*DD + (tx<<2)+cj] = t1[ri][cj];
        __syncthreads();

        float p3[4][4];
        mm_acc(p3, sT, sP, tx, ty);                 // P^3 = T@P (in regs)
        float pold[4][4];
        #pragma unroll
        for (int ri = 0; ri < 4; ri++)
            #pragma unroll
            for (int cj = 0; cj < 4; cj++)
                pold[ri][cj] = sP[((ty<<2)+ri)*DD + (tx<<2)+cj];
        __syncthreads();                            // all reads of P done
        #pragma unroll
        for (int ri = 0; ri < 4; ri++)
            #pragma unroll
            for (int cj = 0; cj < 4; cj++)
                sP[((ty<<2)+ri)*DD + (tx<<2)+cj] = p3[ri][cj];   // P <- P^3
        __syncthreads();

        float f[4][4];
        mm_acc(f, sP, sS, tx, ty);                  // P^3 @ Sigma_N
        __syncthreads();                            // all reads of P^3 done
        #pragma unroll
        for (int ri = 0; ri < 4; ri++)
            #pragma unroll
            for (int cj = 0; cj < 4; cj++)
                sP[((ty<<2)+ri)*DD + (tx<<2)+cj] =
                    -0.5f*pold[ri][cj] + 1.5f*f[ri][cj];
        __syncthreads();
    }

    float w = 1.0f / (1.0f + expf(-xw[0]));
    #pragma unroll
    for (int i = 0; i < 16; i++) {
        int idx = t + i*256;
        g_pw[g*DD*DD + idx] = w * sP[idx];
    }
}

// ---------------------------------------------------------------------------
// Pass 2: out = w*(P@x) + (1-w)*(y/scale)*X, fused. Grid: (CHUNKS, GG, NB).
__global__ __launch_bounds__(256) void k_apply(const float* __restrict__ X,
                                               const float* __restrict__ xw,
                                               float* __restrict__ out) {
    __shared__ float Pt[DD][LDA];   // Pt[d][c'] (transposed w*P)
    __shared__ float As[DD][LDA];   // As[d][k]
    int n = blockIdx.z, g = blockIdx.y, ch = blockIdx.x;
    int t  = threadIdx.x;
    int tx = t & 15, ty = t >> 4;
    const float* base = X   + ((size_t)(n*CC + g*DD))*HW + (size_t)ch*TK;
    float*      obase = out + ((size_t)(n*CC + g*DD))*HW + (size_t)ch*TK;

    // load wP transposed into smem
    #pragma unroll
    for (int i = 0; i < 4; i++) {
        int idx4 = t + i*256;
        int c  = idx4 >> 4;
        int d0 = (idx4 & 15) << 2;
        float4 v = *(const float4*)&g_pw[g*DD*DD + c*DD + d0];
        Pt[d0+0][c] = v.x; Pt[d0+1][c] = v.y;
        Pt[d0+2][c] = v.z; Pt[d0+3][c] = v.w;
    }
    float w = 1.0f / (1.0f + expf(-xw[0]));
    float rscale = rsqrtf(g_varsum * (1.0f/(float)(NB*CC)));
    float coef[4];
    #pragma unroll
    for (int ri = 0; ri < 4; ri++)
        coef[ri] = (1.0f - w) * g_y[n*CC + g*DD + (ty<<2) + ri] * rscale;

    for (int sub = 0; sub < NSUB; sub++) {
        __syncthreads();   // protect As (prev iter reads) and Pt (first iter)
        #pragma unroll
        for (int i = 0; i < 4; i++) {
            int idx = t + i*256;
            int c  = idx >> 4;
            int k4 = (idx & 15) << 2;
            *(float4*)&As[c][k4] = *(const float4*)(base + (size_t)c*HW + sub*SUB + k4);
        }
        __syncthreads();

        float acc[4][4];
        #pragma unroll
        for (int i = 0; i < 4; i++)
            #pragma unroll
            for (int j = 0; j < 4; j++) acc[i][j] = 0.f;

        #pragma unroll 4
        for (int d = 0; d < DD; d++) {
            float4 pv = *(const float4*)&Pt[d][ty<<2];
            float4 xv = *(const float4*)&As[d][tx<<2];
            float p[4] = {pv.x, pv.y, pv.z, pv.w};
            float x[4] = {xv.x, xv.y, xv.z, xv.w};
            #pragma unroll
            for (int ri = 0; ri < 4; ri++)
                #pragma unroll
                for (int cj = 0; cj < 4; cj++)
                    acc[ri][cj] += p[ri]*x[cj];
        }

        // epilogue: add reweight branch, write float4
        #pragma unroll
        for (int ri = 0; ri < 4; ri++) {
            int r = (ty<<2) + ri;
            float4 xs = *(const float4*)&As[r][tx<<2];
            float4 o;
            o.x = acc[ri][0] + coef[ri]*xs.x;
            o.y = acc[ri][1] + coef[ri]*xs.y;
            o.z = acc[ri][2] + coef[ri]*xs.z;
            o.w = acc[ri][3] + coef[ri]*xs.w;
            *(float4*)(obase + (size_t)r*HW + sub*SUB + (tx<<2)) = o;
        }
    }
}

// ---------------------------------------------------------------------------
extern "C" void kernel_launch(void* const* d_in, const int* in_sizes, int n_in,
                              void* d_out, int out_size) {
    const float* X   = (const float*)d_in[0];
    const float* fc1 = (const float*)d_in[1];
    const float* lng = (const float*)d_in[2];
    const float* lnb = (const float*)d_in[3];
    const float* fc2 = (const float*)d_in[4];
    const float* xw  = (const float*)d_in[5];
    float* out = (float*)d_out;

    k_zero<<<64, 256>>>();
    dim3 grid(CHUNKS, GG, NB);
    k_statsgram<<<grid, 256>>>(X);
    k_reweight<<<NB, 256>>>(fc1, lng, lnb, fc2);
    k_sigma<<<GG, 256>>>();
    k_ns<<<GG, 256>>>(xw);
    k_apply<<<grid, 256>>>(X, xw, out);
}